// round 13
// baseline (speedup 1.0000x reference)
#include <cuda_runtime.h>
#include <cuda_fp16.h>
#include <cstdint>

#define N_NODES 100000
#define N_EDGES 1600000
#define IN_DIM 256
#define HID 128
#define OUTD 64
#define DEG_SCALE 1048576.0f          // 2^20 fixed-point for packed degree
#define DEG_INV   (1.0f / 1048576.0f)

// ---------------- scratch (device globals; no allocs allowed) ----------------
__device__ unsigned long long g_degcnt[N_NODES];  // hi32: count, lo32: fixed-point sum(w)
__device__ float g_dinv[N_NODES];
__device__ int   g_off[N_NODES];
__device__ int   g_cur[N_NODES];
__device__ int   g_cnt[N_NODES];
__device__ int   g_total;
__device__ int2  g_edge[N_EDGES];   // {src, float_bits(w * dinv[col] * dinv[row])}
__device__ __half g_W1h[HID * IN_DIM];   // W1 fp16, [n][k]
__device__ __half g_W2h[OUTD * HID];     // W2 fp16, [n][k]
__device__ __half g_h1[(size_t)N_NODES * HID];  // fp16: x @ W1 (unscaled)
__device__ __half g_a1[(size_t)N_NODES * HID];  // fp16: relu(agg + b1)
__device__ __half g_h2[(size_t)N_NODES * OUTD]; // fp16: a1 @ W2 (unscaled)

__device__ __forceinline__ uint32_t smem_u32(const void* p) {
    uint32_t a;
    asm("{ .reg .u64 t; cvta.to.shared.u64 t, %1; cvt.u32.u64 %0, t; }" : "=r"(a) : "l"(p));
    return a;
}
__device__ __forceinline__ void ldm4(uint32_t* r, uint32_t addr) {
    asm volatile("ldmatrix.sync.aligned.m8n8.x4.shared.b16 {%0,%1,%2,%3}, [%4];"
                 : "=r"(r[0]), "=r"(r[1]), "=r"(r[2]), "=r"(r[3]) : "r"(addr));
}
__device__ __forceinline__ void mma_f16(float* d, const uint32_t* a, const uint32_t* b) {
    asm volatile(
        "mma.sync.aligned.m16n8k16.row.col.f32.f16.f16.f32 "
        "{%0,%1,%2,%3}, {%4,%5,%6,%7}, {%8,%9}, {%0,%1,%2,%3};"
        : "+f"(d[0]), "+f"(d[1]), "+f"(d[2]), "+f"(d[3])
        : "r"(a[0]), "r"(a[1]), "r"(a[2]), "r"(a[3]), "r"(b[0]), "r"(b[1]));
}
__device__ __forceinline__ float4 ld_h4(const __half* p) {
    uint2 u = *(const uint2*)p;
    __half2 a = *(__half2*)&u.x, b = *(__half2*)&u.y;
    float2 fa = __half22float2(a), fb = __half22float2(b);
    return make_float4(fa.x, fa.y, fb.x, fb.y);
}
__device__ __forceinline__ void cp_async16(void* smem, const void* gmem) {
    unsigned s = (unsigned)__cvta_generic_to_shared(smem);
    asm volatile("cp.async.cg.shared.global [%0], [%1], 16;" :: "r"(s), "l"(gmem));
}
#define CP_COMMIT() asm volatile("cp.async.commit_group;")
#define CP_WAIT(n)  asm volatile("cp.async.wait_group %0;" :: "n"(n))

// ---------------- fused setup ----------------
__global__ void k_setup(const float* __restrict__ W1, const float* __restrict__ W2) {
    int i = blockIdx.x * blockDim.x + threadIdx.x;
    if (i < N_NODES) g_degcnt[i] = 0ull;
    if (i == 0) g_total = 0;
    if (i < HID * IN_DIM) {              // W1: [k][n] f32 -> [n][k] fp16
        int n = i >> 8, k = i & 255;
        g_W1h[i] = __float2half(W1[(size_t)k * HID + n]);
    }
    if (i < OUTD * HID) {                // W2: [k][n] f32 -> [n][k] fp16
        int n = i >> 7, k = i & 127;
        g_W2h[i] = __float2half(W2[(size_t)k * OUTD + n]);
    }
}

// ---------------- histogram: one packed 64-bit atomic per edge ----------------
__global__ void k_hist(const int* __restrict__ col, const float* __restrict__ w) {
    int e = (blockIdx.x * blockDim.x + threadIdx.x) * 2;
    if (e + 1 < N_EDGES) {
        int2 c = *(const int2*)(col + e);
        float2 ww = *(const float2*)(w + e);
        unsigned long long p0 = (1ull << 32) | (unsigned long long)__float2uint_rn(ww.x * DEG_SCALE);
        unsigned long long p1 = (1ull << 32) | (unsigned long long)__float2uint_rn(ww.y * DEG_SCALE);
        atomicAdd(&g_degcnt[c.x], p0);
        atomicAdd(&g_degcnt[c.y], p1);
    } else if (e < N_EDGES) {
        unsigned long long p0 = (1ull << 32) | (unsigned long long)__float2uint_rn(w[e] * DEG_SCALE);
        atomicAdd(&g_degcnt[col[e]], p0);
    }
}

// ---------------- fused dinv + CSR bucket allocation ----------------
__global__ void __launch_bounds__(256) k_dinvalloc() {
    __shared__ int sc[256];
    __shared__ int sbase;
    int tid = threadIdx.x;
    int i = blockIdx.x * 256 + tid;
    int v = 0;
    if (i < N_NODES) {
        unsigned long long dc = g_degcnt[i];
        v = (int)(dc >> 32);
        float d = 1.0f + (float)(unsigned)(dc & 0xFFFFFFFFull) * DEG_INV;  // +1 self-loop
        g_dinv[i] = rsqrtf(d);       // d >= 1 always
        g_cnt[i] = v;
    }
    sc[tid] = v;
    __syncthreads();
#pragma unroll
    for (int off = 1; off < 256; off <<= 1) {
        int t = (tid >= off) ? sc[tid - off] : 0;
        __syncthreads();
        sc[tid] += t;
        __syncthreads();
    }
    if (tid == 255) sbase = atomicAdd(&g_total, sc[255]);
    __syncthreads();
    if (i < N_NODES) {
        int base = sbase + sc[tid] - v;
        g_off[i] = base;
        g_cur[i] = base;
    }
}

// ---------------- CSR fill: packed int2 payload ----------------
__global__ void k_fill(const int* __restrict__ row, const int* __restrict__ col,
                       const float* __restrict__ w) {
    int e = (blockIdx.x * blockDim.x + threadIdx.x) * 2;
    if (e + 1 < N_EDGES) {
        int2 r = *(const int2*)(row + e);
        int2 c = *(const int2*)(col + e);
        float2 ww = *(const float2*)(w + e);
        float w0 = ww.x * g_dinv[c.x] * g_dinv[r.x];
        float w1 = ww.y * g_dinv[c.y] * g_dinv[r.y];
        int p0 = atomicAdd(&g_cur[c.x], 1);
        g_edge[p0] = make_int2(r.x, __float_as_int(w0));
        int p1 = atomicAdd(&g_cur[c.y], 1);
        g_edge[p1] = make_int2(r.y, __float_as_int(w1));
    } else if (e < N_EDGES) {
        float w0 = w[e] * g_dinv[col[e]] * g_dinv[row[e]];
        int pos = atomicAdd(&g_cur[col[e]], 1);
        g_edge[pos] = make_int2(row[e], __float_as_int(w0));
    }
}

// ---------------- GEMM1: fp16 HMMA, 2-stage double buffer ----------------
// C[100000,128] = x @ W1; BM=128 BN=128 BK=32, 256 thr (8 warps 4x2).
#define APAD 40
__global__ void __launch_bounds__(256, 2) k_gemm1_mma(const float* __restrict__ x) {
    __shared__ __align__(16) __half sA[2][128 * APAD];
    __shared__ __align__(16) __half sB[2][128 * APAD];

    int tid = threadIdx.x;
    int lane = tid & 31;
    int wid = tid >> 5;
    int wm = (wid & 3) * 32;
    int wn = (wid >> 2) * 64;
    int row0 = blockIdx.x * 128;

    int within = lane & 7, sub = lane >> 3;
    int aRow = within + (sub & 1) * 8;
    int aK   = (sub >> 1) * 8;
    int bN   = within + (sub >> 1) * 8;
    int bK   = (sub & 1) * 8;

    float acc[2][8][4];
#pragma unroll
    for (int mf = 0; mf < 2; mf++)
#pragma unroll
        for (int nf = 0; nf < 8; nf++)
#pragma unroll
            for (int q = 0; q < 4; q++) acc[mf][nf][q] = 0.0f;

    int fr = tid >> 1;
    int fhalf = tid & 1;
    int grow = row0 + fr;
    bool aok = grow < N_NODES;
    const float* asrc = x + (size_t)grow * IN_DIM + fhalf * 16;
    const float4 z4 = make_float4(0.f, 0.f, 0.f, 0.f);

    // B tile: 128 n-rows x 32 k halves = 512 16B-chunks, 2 per thread
    auto issueB = [&](int kt, int stage) {
#pragma unroll
        for (int j = 0; j < 2; j++) {
            int i = tid + j * 256;           // 0..511
            int n = i >> 2, c8 = (i & 3) * 8;
            cp_async16(&sB[stage][n * APAD + c8], g_W1h + (size_t)n * IN_DIM + kt + c8);
        }
        CP_COMMIT();
    };
    // A store: 16 halves per thread as 2x STS.128 (16B aligned: 80B row pitch, 32B col)
    auto storeA = [&](const float4* ra, int stage) {
        __half2 h[8];
#pragma unroll
        for (int j = 0; j < 4; j++) {
            h[j * 2]     = __floats2half2_rn(ra[j].x, ra[j].y);
            h[j * 2 + 1] = __floats2half2_rn(ra[j].z, ra[j].w);
        }
        uint4* dst = (uint4*)&sA[stage][fr * APAD + fhalf * 16];
        dst[0] = *(uint4*)&h[0];
        dst[1] = *(uint4*)&h[4];
    };

    float4 ra[4];
#pragma unroll
    for (int j = 0; j < 4; j++) ra[j] = aok ? *(const float4*)(asrc + j * 4) : z4;
    issueB(0, 0);
    storeA(ra, 0);
#pragma unroll
    for (int j = 0; j < 4; j++) ra[j] = aok ? *(const float4*)(asrc + 32 + j * 4) : z4;
    CP_WAIT(0);
    __syncthreads();

#pragma unroll 1
    for (int t = 0; t < 8; t++) {
        int cur = t & 1, nxt = cur ^ 1;
        if (t < 7) {
            issueB((t + 1) * 32, nxt);
            storeA(ra, nxt);
            if (t < 6) {
#pragma unroll
                for (int j = 0; j < 4; j++)
                    ra[j] = aok ? *(const float4*)(asrc + (t + 2) * 32 + j * 4) : z4;
            }
        }
        uint32_t aB = smem_u32(sA[cur]);
        uint32_t bB = smem_u32(sB[cur]);
#pragma unroll
        for (int kf = 0; kf < 2; kf++) {
            int kk = kf * 16;
            uint32_t af[2][4];
#pragma unroll
            for (int mf = 0; mf < 2; mf++)
                ldm4(af[mf], aB + (uint32_t)((wm + mf * 16 + aRow) * APAD + kk + aK) * 2);
#pragma unroll
            for (int np = 0; np < 4; np++) {
                uint32_t bf[4];
                ldm4(bf, bB + (uint32_t)((wn + np * 16 + bN) * APAD + kk + bK) * 2);
#pragma unroll
                for (int s = 0; s < 2; s++) {
                    int nf = np * 2 + s;
#pragma unroll
                    for (int mf = 0; mf < 2; mf++)
                        mma_f16(acc[mf][nf], af[mf], bf + s * 2);
                }
            }
        }
        if (t < 7) {
            CP_WAIT(0);
            __syncthreads();
        }
    }

    // epilogue: g_h1 (fp16) = C (unscaled)
    int g = lane >> 2, t4 = lane & 3;
#pragma unroll
    for (int mf = 0; mf < 2; mf++) {
        int r0 = row0 + wm + mf * 16 + g;
        int r1 = r0 + 8;
#pragma unroll
        for (int nf = 0; nf < 8; nf++) {
            int cb = wn + nf * 8 + t4 * 2;
            if (r0 < N_NODES)
                *(__half2*)(g_h1 + (size_t)r0 * HID + cb) =
                    __floats2half2_rn(acc[mf][nf][0], acc[mf][nf][1]);
            if (r1 < N_NODES)
                *(__half2*)(g_h1 + (size_t)r1 * HID + cb) =
                    __floats2half2_rn(acc[mf][nf][2], acc[mf][nf][3]);
        }
    }
}

// ---------------- layer-1 aggregation + bias + relu -> fp16 a1 ----------------
__global__ void k_agg1(const float* __restrict__ b1) {
    int gw = (blockIdx.x * blockDim.x + threadIdx.x) >> 5;
    if (gw >= N_NODES) return;
    int lane = threadIdx.x & 31;
    const __half* hbase = g_h1;
    int doff = lane * 4;

    float4 selfv = ld_h4(hbase + (size_t)gw * HID + doff);
    float4 acc0 = make_float4(0.f, 0.f, 0.f, 0.f);
    float4 acc1 = make_float4(0.f, 0.f, 0.f, 0.f);

    int beg = g_off[gw];
    int end = beg + g_cnt[gw];
    int e = beg;
    for (; e + 2 <= end; e += 2) {
        int2 e0 = g_edge[e];
        int2 e1 = g_edge[e + 1];
        float w0 = __int_as_float(e0.y), w1 = __int_as_float(e1.y);
        float4 v0 = ld_h4(hbase + (size_t)e0.x * HID + doff);
        float4 v1 = ld_h4(hbase + (size_t)e1.x * HID + doff);
        acc0.x = fmaf(w0, v0.x, acc0.x); acc0.y = fmaf(w0, v0.y, acc0.y);
        acc0.z = fmaf(w0, v0.z, acc0.z); acc0.w = fmaf(w0, v0.w, acc0.w);
        acc1.x = fmaf(w1, v1.x, acc1.x); acc1.y = fmaf(w1, v1.y, acc1.y);
        acc1.z = fmaf(w1, v1.z, acc1.z); acc1.w = fmaf(w1, v1.w, acc1.w);
    }
    if (e < end) {
        int2 e0 = g_edge[e];
        float w0 = __int_as_float(e0.y);
        float4 v0 = ld_h4(hbase + (size_t)e0.x * HID + doff);
        acc0.x = fmaf(w0, v0.x, acc0.x); acc0.y = fmaf(w0, v0.y, acc0.y);
        acc0.z = fmaf(w0, v0.z, acc0.z); acc0.w = fmaf(w0, v0.w, acc0.w);
    }
    float s = g_dinv[gw];
    float s2 = s * s;
    float4 bb = *(const float4*)(b1 + doff);
    float rx = fmaxf(fmaf(s2, selfv.x, acc0.x + acc1.x) + bb.x, 0.f);
    float ry = fmaxf(fmaf(s2, selfv.y, acc0.y + acc1.y) + bb.y, 0.f);
    float rz = fmaxf(fmaf(s2, selfv.z, acc0.z + acc1.z) + bb.z, 0.f);
    float rw = fmaxf(fmaf(s2, selfv.w, acc0.w + acc1.w) + bb.w, 0.f);
    *(__half2*)(g_a1 + (size_t)gw * HID + doff)     = __floats2half2_rn(rx, ry);
    *(__half2*)(g_a1 + (size_t)gw * HID + doff + 2) = __floats2half2_rn(rz, rw);
}

// ---------------- GEMM2: fp16 HMMA, all-cp.async, 2-stage ----------------
// C[100000,64] = a1 @ W2; BM=128 BN=64 BK=32.
__global__ void __launch_bounds__(256, 2) k_gemm2_mma() {
    __shared__ __align__(16) __half sA[2][128 * APAD];
    __shared__ __align__(16) __half sB[2][64 * APAD];

    int tid = threadIdx.x;
    int lane = tid & 31;
    int wid = tid >> 5;
    int wm = (wid & 3) * 32;
    int wn = (wid >> 2) * 32;
    int row0 = blockIdx.x * 128;

    int within = lane & 7, sub = lane >> 3;
    int aRow = within + (sub & 1) * 8;
    int aK   = (sub >> 1) * 8;
    int bN   = within + (sub >> 1) * 8;
    int bK   = (sub & 1) * 8;

    float acc[2][4][4];
#pragma unroll
    for (int mf = 0; mf < 2; mf++)
#pragma unroll
        for (int nf = 0; nf < 4; nf++)
#pragma unroll
            for (int q = 0; q < 4; q++) acc[mf][nf][q] = 0.0f;

    auto issueAB = [&](int kt, int stage) {
#pragma unroll
        for (int j = 0; j < 2; j++) {
            int i = tid + j * 256;
            int r = i >> 2, c8 = (i & 3) * 8;
            int gr = row0 + r;
            if (gr >= N_NODES) gr = N_NODES - 1;   // clamp: values unused, stay in-bounds
            cp_async16(&sA[stage][r * APAD + c8], g_a1 + (size_t)gr * HID + kt + c8);
        }
        {
            int n = tid >> 2, c8 = (tid & 3) * 8;
            cp_async16(&sB[stage][n * APAD + c8], g_W2h + (size_t)n * HID + kt + c8);
        }
        CP_COMMIT();
    };

    issueAB(0, 0);
    CP_WAIT(0);
    __syncthreads();

#pragma unroll 1
    for (int t = 0; t < 4; t++) {
        int cur = t & 1, nxt = cur ^ 1;
        if (t < 3) issueAB((t + 1) * 32, nxt);

        uint32_t aB = smem_u32(sA[cur]);
        uint32_t bB = smem_u32(sB[cur]);
#pragma unroll
        for (int kf = 0; kf < 2; kf++) {
            int kk = kf * 16;
            uint32_t af[2][4];
#pragma unroll
            for (int mf = 0; mf < 2; mf++)
                ldm4(af[mf], aB + (uint32_t)((wm + mf * 16 + aRow) * APAD + kk + aK) * 2);
#pragma unroll
            for (int np = 0; np < 2; np++) {
                uint32_t bf[4];
                ldm4(bf, bB + (uint32_t)((wn + np * 16 + bN) * APAD + kk + bK) * 2);
#pragma unroll
                for (int s = 0; s < 2; s++) {
                    int nf = np * 2 + s;
#pragma unroll
                    for (int mf = 0; mf < 2; mf++)
                        mma_f16(acc[mf][nf], af[mf], bf + s * 2);
                }
            }
        }
        if (t < 3) {
            CP_WAIT(0);
            __syncthreads();
        }
    }

    int g = lane >> 2, t4 = lane & 3;
#pragma unroll
    for (int mf = 0; mf < 2; mf++) {
        int r0 = row0 + wm + mf * 16 + g;
        int r1 = r0 + 8;
#pragma unroll
        for (int nf = 0; nf < 4; nf++) {
            int cb = wn + nf * 8 + t4 * 2;
            if (r0 < N_NODES)
                *(__half2*)(g_h2 + (size_t)r0 * OUTD + cb) =
                    __floats2half2_rn(acc[mf][nf][0], acc[mf][nf][1]);
            if (r1 < N_NODES)
                *(__half2*)(g_h2 + (size_t)r1 * OUTD + cb) =
                    __floats2half2_rn(acc[mf][nf][2], acc[mf][nf][3]);
        }
    }
}

// ---------------- layer-2 aggregation ----------------
__global__ void k_agg2(const float* __restrict__ b2, float* __restrict__ out) {
    int gw = (blockIdx.x * blockDim.x + threadIdx.x) >> 5;
    if (gw >= N_NODES) return;
    int lane = threadIdx.x & 31;
    int doff = lane * 2;

    float2 selfv = __half22float2(*(const __half2*)(g_h2 + (size_t)gw * OUTD + doff));
    float2 acc0 = make_float2(0.f, 0.f);
    float2 acc1 = make_float2(0.f, 0.f);

    int beg = g_off[gw];
    int end = beg + g_cnt[gw];
    int e = beg;
    for (; e + 2 <= end; e += 2) {
        int2 e0 = g_edge[e];
        int2 e1 = g_edge[e + 1];
        float w0 = __int_as_float(e0.y), w1 = __int_as_float(e1.y);
        float2 v0 = __half22float2(*(const __half2*)(g_h2 + (size_t)e0.x * OUTD + doff));
        float2 v1 = __half22float2(*(const __half2*)(g_h2 + (size_t)e1.x * OUTD + doff));
        acc0.x = fmaf(w0, v0.x, acc0.x); acc0.y = fmaf(w0, v0.y, acc0.y);
        acc1.x = fmaf(w1, v1.x, acc1.x); acc1.y = fmaf(w1, v1.y, acc1.y);
    }
    if (e < end) {
        int2 e0 = g_edge[e];
        float w0 = __int_as_float(e0.y);
        float2 v0 = __half22float2(*(const __half2*)(g_h2 + (size_t)e0.x * OUTD + doff));
        acc0.x = fmaf(w0, v0.x, acc0.x); acc0.y = fmaf(w0, v0.y, acc0.y);
    }
    float s = g_dinv[gw];
    float s2 = s * s;
    float2 bb = ((const float2*)b2)[lane];
    float2 r = make_float2(fmaf(s2, selfv.x, acc0.x + acc1.x) + bb.x,
                           fmaf(s2, selfv.y, acc0.y + acc1.y) + bb.y);
    *(float2*)(out + (size_t)gw * OUTD + doff) = r;
}

// ---------------- launch: single stream ----------------
extern "C" void kernel_launch(void* const* d_in, const int* in_sizes, int n_in,
                              void* d_out, int out_size) {
    const float* x  = (const float*)d_in[0];
    const int*   ei = (const int*)d_in[1];   // int32 (JAX downgrades int64)
    const float* ew = (const float*)d_in[2];
    const float* W1 = (const float*)d_in[3];
    const float* b1 = (const float*)d_in[4];
    const float* W2 = (const float*)d_in[5];
    const float* b2 = (const float*)d_in[6];
    float*       out = (float*)d_out;

    const int* row = ei;
    const int* col = ei + N_EDGES;

    k_setup<<<(N_NODES + 255) / 256, 256>>>(W1, W2);                 // 0
    k_hist<<<(N_EDGES / 2 + 255) / 256, 256>>>(col, ew);             // 1
    k_dinvalloc<<<(N_NODES + 255) / 256, 256>>>();                   // 2
    k_gemm1_mma<<<(N_NODES + 127) / 128, 256>>>(x);                  // 3 (profiled slot)
    k_fill<<<(N_EDGES / 2 + 255) / 256, 256>>>(row, col, ew);        // 4
    k_agg1<<<(N_NODES * 32 + 255) / 256, 256>>>(b1);                 // 5
    k_gemm2_mma<<<(N_NODES + 127) / 128, 256>>>();                   // 6
    k_agg2<<<(N_NODES * 32 + 255) / 256, 256>>>(b2, out);            // 7
}